// round 7
// baseline (speedup 1.0000x reference)
#include <cuda_runtime.h>
#include <cuda_bf16.h>
#include <math_constants.h>

// Problem constants
#define B_    8
#define C_    192
#define NP_   3136
#define K_    9
#define COUT_ 384
#define M2_   768   // 2*COUT rows in fused weight

// Scratch (device globals — allowed; no runtime allocation)
__device__ float g_W[M2_ * C_];                      // fused weight [768][192]
__device__ float g_T[(size_t)B_ * NP_ * M2_];        // table [B][N][768] ~77MB

// ---------------------------------------------------------------------------
// Kernel 1: build fused weight matrix.
// rows [0,384):   Wc = W[:, 0:C] - W[:, C:2C]   (multiplies center features)
// rows [384,768): Wn = W[:, C:2C]               (multiplies neighbor features)
// W layout: [COUT, 2C] row-major.
// ---------------------------------------------------------------------------
__global__ void prep_w_kernel(const float* __restrict__ W) {
    int i = blockIdx.x * 256 + threadIdx.x;
    if (i >= M2_ * C_) return;
    int row = i / C_;
    int k   = i % C_;
    float v;
    if (row < COUT_) {
        v = W[row * (2 * C_) + k] - W[row * (2 * C_) + C_ + k];
    } else {
        v = W[(row - COUT_) * (2 * C_) + C_ + k];
    }
    g_W[i] = v;
}

// ---------------------------------------------------------------------------
// Kernel 2: GEMM  T[b][n][m] = sum_k g_W[m][k] * x[b][k][n]
// M=768, Kdim=192, Ncols=3136 per batch. Tiled fp32: BM=128, BN=64, BK=16.
// 256 threads, each computes 8x4 micro-tile.
// ---------------------------------------------------------------------------
#define BM 128
#define BN 64
#define BK 16
#define TM 8
#define TN 4

__global__ __launch_bounds__(256) void gemm_kernel(const float* __restrict__ x) {
    __shared__ float As[BK][BM];      // A transposed: [k][m]
    __shared__ float Bs[BK][BN + 1];  // pad to dodge bank conflicts

    const int b  = blockIdx.z;
    const int m0 = blockIdx.x * BM;   // 0..5
    const int n0 = blockIdx.y * BN;   // 0..48

    const float* xb = x + (size_t)b * C_ * NP_;   // [C][NP]

    const int tid  = threadIdx.x;     // 0..255
    const int aRow = tid / BK;        // 0..15
    const int aK   = tid % BK;        // 0..15
    const int bK   = tid / BN;        // 0..3
    const int bN   = tid % BN;        // 0..63
    const int tm   = tid / 16;        // 0..15 -> rows tm*8..tm*8+7
    const int tn   = tid % 16;        // 0..15 -> cols tn*4..tn*4+3

    float acc[TM][TN];
    #pragma unroll
    for (int i = 0; i < TM; ++i)
        #pragma unroll
        for (int j = 0; j < TN; ++j) acc[i][j] = 0.f;

    for (int k0 = 0; k0 < C_; k0 += BK) {
        // Load A tile (g_W rows m0..m0+127, cols k0..k0+15) transposed into As
        #pragma unroll
        for (int p = 0; p < BM / 16; ++p) {
            As[aK][aRow + p * 16] = g_W[(m0 + aRow + p * 16) * C_ + k0 + aK];
        }
        // Load B tile: x[b][k0+kk][n0+nn], coalesced over n
        #pragma unroll
        for (int p = 0; p < BK / 4; ++p) {
            Bs[bK + p * 4][bN] = xb[(size_t)(k0 + bK + p * 4) * NP_ + n0 + bN];
        }
        __syncthreads();

        #pragma unroll
        for (int kk = 0; kk < BK; ++kk) {
            float a[TM], bb[TN];
            #pragma unroll
            for (int i = 0; i < TM; ++i) a[i] = As[kk][tm * TM + i];
            #pragma unroll
            for (int j = 0; j < TN; ++j) bb[j] = Bs[kk][tn * TN + j];
            #pragma unroll
            for (int i = 0; i < TM; ++i)
                #pragma unroll
                for (int j = 0; j < TN; ++j)
                    acc[i][j] = fmaf(a[i], bb[j], acc[i][j]);
        }
        __syncthreads();
    }

    // Write T[b][n][m] — gather-friendly layout (m contiguous per point)
    #pragma unroll
    for (int j = 0; j < TN; ++j) {
        const int n = n0 + tn * TN + j;
        float* dst = &g_T[((size_t)b * NP_ + n) * M2_ + m0 + tm * TM];
        #pragma unroll
        for (int i = 0; i < TM; ++i) dst[i] = acc[i][j];
    }
}

// ---------------------------------------------------------------------------
// Kernel 3: gather + max + bias + relu.
// out[b][o][n] = relu( max_k( T[b][ci[k]][o] + T[b][ni[k]][384+o] ) + bias[o] )
// One block per (b,n); 128 threads cover o in 3 strided passes.
// Reads are coalesced over o (contiguous in T's last dim).
// estride: 1 if edge_index materialized as int32; 2 if raw int64 little-endian
// (low word at even int32 offset).
// ---------------------------------------------------------------------------
__global__ __launch_bounds__(128) void gather_max_kernel(
    const int* __restrict__ e,
    const float* __restrict__ bias,
    float* __restrict__ out,
    int estride)
{
    const int bn = blockIdx.x;            // b*NP + n
    const int b  = bn / NP_;
    const int n  = bn % NP_;

    __shared__ int ci[K_], ni[K_];
    const int tid = threadIdx.x;
    if (tid < K_) {
        size_t ebase = ((size_t)bn * K_ + tid) * estride;
        size_t half  = (size_t)B_ * NP_ * K_ * estride;
        int nv = e[ebase];                 // edge_index[0] = neighbor
        int cv = e[half + ebase];          // edge_index[1] = center
        // Clamp defensively: guarantees no illegal access even if layout
        // assumption is wrong (then rel_err fails instead of crashing).
        ni[tid] = min(max(nv, 0), NP_ - 1);
        ci[tid] = min(max(cv, 0), NP_ - 1);
    }
    __syncthreads();

    const float* Tb = &g_T[(size_t)b * NP_ * M2_];

    #pragma unroll
    for (int r = 0; r < 3; ++r) {
        const int o = tid + r * 128;
        float m = -CUDART_INF_F;
        #pragma unroll
        for (int k = 0; k < K_; ++k) {
            float v = __ldg(&Tb[(size_t)ci[k] * M2_ + o]) +
                      __ldg(&Tb[(size_t)ni[k] * M2_ + COUT_ + o]);
            m = fmaxf(m, v);
        }
        out[((size_t)b * COUT_ + o) * NP_ + n] = fmaxf(m + bias[o], 0.f);
    }
}

// ---------------------------------------------------------------------------
extern "C" void kernel_launch(void* const* d_in, const int* in_sizes, int n_in,
                              void* d_out, int out_size) {
    const float* x    = (const float*)d_in[0];
    const int*   e    = (const int*)d_in[1];
    const float* W    = (const float*)d_in[2];
    const float* bias = (const float*)d_in[3];
    float*       out  = (float*)d_out;

    // Logical edge count is 2*B*N*K = 451584 int64 values.
    // If the harness materialized them as int32, in_sizes[1] == 451584 (stride 1).
    // If it kept raw int64 bytes viewed as int32, in_sizes[1] == 903168 (stride 2,
    // little-endian low word first).
    const int n_edge_logical = 2 * B_ * NP_ * K_;
    const int estride = (in_sizes[1] >= 2 * n_edge_logical) ? 2 : 1;

    prep_w_kernel<<<(M2_ * C_ + 255) / 256, 256>>>(W);

    dim3 gemm_grid(M2_ / BM, NP_ / BN, B_);   // (6, 49, 8)
    gemm_kernel<<<gemm_grid, 256>>>(x);

    gather_max_kernel<<<B_ * NP_, 128>>>(e, bias, out, estride);
}

// round 10
// speedup vs baseline: 2.6523x; 2.6523x over previous
#include <cuda_runtime.h>
#include <cuda_bf16.h>
#include <math_constants.h>

// Problem constants
#define B_    8
#define C_    192
#define NP_   3136
#define K_    9
#define COUT_ 384
#define M2_   768   // 2*COUT rows in fused weight

// Scratch (device globals)
__device__ float g_Wt[C_ * M2_];                     // fused weight, [k][m], tf32-rounded
__device__ float g_T[(size_t)B_ * NP_ * M2_];        // table [B][N][768] ~77MB

__device__ __forceinline__ unsigned f2tf32(float f) {
    unsigned r;
    asm("cvt.rna.tf32.f32 %0, %1;" : "=r"(r) : "f"(f));
    return r;
}

// ---------------------------------------------------------------------------
// Kernel 1: build fused, transposed, tf32-rounded weight g_Wt[k][m]:
//   m <  384: Wc[m][k] = W[m][k] - W[m][C+k]   (center)
//   m >= 384: Wn[m'][k] = W[m'][C+k]           (neighbor), m' = m-384
// W layout: [COUT][2C] row-major.
// ---------------------------------------------------------------------------
__global__ void prep_w_kernel(const float* __restrict__ W) {
    int i = blockIdx.x * 256 + threadIdx.x;
    if (i >= C_ * M2_) return;
    int k = i / M2_;
    int m = i % M2_;
    float v;
    if (m < COUT_) {
        v = W[m * (2 * C_) + k] - W[m * (2 * C_) + C_ + k];
    } else {
        v = W[(m - COUT_) * (2 * C_) + C_ + k];
    }
    unsigned t = f2tf32(v);
    g_Wt[i] = __uint_as_float(t);
}

// ---------------------------------------------------------------------------
// Kernel 2: tf32 tensor-core GEMM
//   T[b][n][m] = sum_k x[b][k][n] * Wt[k][m]   (+ bias[m] for m<384)
// mma.m16n8k8: mma-M = n (16), mma-N = m (8), mma-K = k (8).
// Block tile: 64n x 128m, 256 threads = 8 warps (2 n-warps x 4 m-warps),
// warp tile 32n x 32m. K chunked by 16, double-buffered smem.
// ---------------------------------------------------------------------------
#define KC 16
#define XPAD 68    // 64 + 4 (68*4=272 bytes, 16B aligned rows, 2-way LDS conflicts max)
#define WPAD 132   // 128 + 4 (528 bytes, 16B aligned rows)

__global__ __launch_bounds__(256) void gemm_tf32_kernel(
    const float* __restrict__ x, const float* __restrict__ bias)
{
    __shared__ float Xs[2][KC][XPAD];   // [stage][k][n]
    __shared__ float Ws[2][KC][WPAD];   // [stage][k][m]

    const int b  = blockIdx.z;
    const int m0 = blockIdx.x * 128;    // 0..5 * 128
    const int n0 = blockIdx.y * 64;     // 0..48 * 64

    const float* xb = x + (size_t)b * C_ * NP_;

    const int tid  = threadIdx.x;
    const int warp = tid >> 5;
    const int lane = tid & 31;
    const int g    = lane >> 2;         // groupID 0..7
    const int tig  = lane & 3;          // thread-in-group 0..3
    const int wn   = warp & 1;          // n-warp: offset 32*wn
    const int wm   = warp >> 1;         // m-warp: offset 32*wm
    const int nW   = wn * 32;
    const int mW   = wm * 32;

    float acc[2][4][4];
    #pragma unroll
    for (int nt = 0; nt < 2; ++nt)
        #pragma unroll
        for (int mt = 0; mt < 4; ++mt)
            #pragma unroll
            for (int r = 0; r < 4; ++r) acc[nt][mt][r] = 0.f;

    // ---- tile loader: chunk c (k0 = c*KC) into stage s ----
    auto load_stage = [&](int s, int c) {
        const int k0 = c * KC;
        // X: 16k x 64n = 256 float4, one per thread
        {
            int kk = tid >> 4;          // 0..15
            int nq = tid & 15;          // 0..15
            const float4 v = *reinterpret_cast<const float4*>(
                &xb[(size_t)(k0 + kk) * NP_ + n0 + nq * 4]);
            float4 t;
            t.x = __uint_as_float(f2tf32(v.x));
            t.y = __uint_as_float(f2tf32(v.y));
            t.z = __uint_as_float(f2tf32(v.z));
            t.w = __uint_as_float(f2tf32(v.w));
            *reinterpret_cast<float4*>(&Xs[s][kk][nq * 4]) = t;
        }
        // W: 16k x 128m = 512 float4, two per thread (already tf32-rounded)
        #pragma unroll
        for (int r = 0; r < 2; ++r) {
            int i  = tid + r * 256;
            int kk = i >> 5;            // 0..15
            int mq = i & 31;            // 0..31
            const float4 v = *reinterpret_cast<const float4*>(
                &g_Wt[(size_t)(k0 + kk) * M2_ + m0 + mq * 4]);
            *reinterpret_cast<float4*>(&Ws[s][kk][mq * 4]) = v;
        }
    };

    load_stage(0, 0);
    __syncthreads();

    const int NCHUNK = C_ / KC;   // 12
    for (int c = 0; c < NCHUNK; ++c) {
        const int s = c & 1;
        if (c + 1 < NCHUNK) load_stage(s ^ 1, c + 1);

        #pragma unroll
        for (int ks = 0; ks < 2; ++ks) {
            const int kb = ks * 8;
            unsigned a[2][4], bf[4][2];
            // A fragments (rows = n, cols = k):
            // a0:(n+g, k+tig) a1:(n+g+8, k+tig) a2:(n+g, k+tig+4) a3:(n+g+8, k+tig+4)
            #pragma unroll
            for (int nt = 0; nt < 2; ++nt) {
                const int nb = nW + nt * 16;
                a[nt][0] = __float_as_uint(Xs[s][kb + tig    ][nb + g    ]);
                a[nt][1] = __float_as_uint(Xs[s][kb + tig    ][nb + g + 8]);
                a[nt][2] = __float_as_uint(Xs[s][kb + tig + 4][nb + g    ]);
                a[nt][3] = __float_as_uint(Xs[s][kb + tig + 4][nb + g + 8]);
            }
            // B fragments (rows = k, cols = m): b0:(k+tig, m+g) b1:(k+tig+4, m+g)
            #pragma unroll
            for (int mt = 0; mt < 4; ++mt) {
                const int mb = mW + mt * 8;
                bf[mt][0] = __float_as_uint(Ws[s][kb + tig    ][mb + g]);
                bf[mt][1] = __float_as_uint(Ws[s][kb + tig + 4][mb + g]);
            }
            #pragma unroll
            for (int nt = 0; nt < 2; ++nt)
                #pragma unroll
                for (int mt = 0; mt < 4; ++mt) {
                    asm volatile(
                        "mma.sync.aligned.m16n8k8.row.col.f32.tf32.tf32.f32 "
                        "{%0,%1,%2,%3}, {%4,%5,%6,%7}, {%8,%9}, {%0,%1,%2,%3};"
                        : "+f"(acc[nt][mt][0]), "+f"(acc[nt][mt][1]),
                          "+f"(acc[nt][mt][2]), "+f"(acc[nt][mt][3])
                        : "r"(a[nt][0]), "r"(a[nt][1]), "r"(a[nt][2]), "r"(a[nt][3]),
                          "r"(bf[mt][0]), "r"(bf[mt][1]));
                }
        }
        __syncthreads();
    }

    // ---- epilogue: + bias (center half only), write T[b][n][m] ----
    // D layout: c0:(row g, col tig*2) c1:(g, tig*2+1) c2:(g+8, tig*2) c3:(g+8, tig*2+1)
    const bool addb = (m0 < COUT_);   // 384 boundary is 128-aligned -> uniform per block
    float* Tb = &g_T[(size_t)b * NP_ * M2_];
    #pragma unroll
    for (int nt = 0; nt < 2; ++nt) {
        #pragma unroll
        for (int mt = 0; mt < 4; ++mt) {
            const int n = n0 + nW + nt * 16 + g;
            const int m = m0 + mW + mt * 8 + tig * 2;
            float b0 = 0.f, b1 = 0.f;
            if (addb) { b0 = bias[m]; b1 = bias[m + 1]; }
            float2 v0 = make_float2(acc[nt][mt][0] + b0, acc[nt][mt][1] + b1);
            float2 v1 = make_float2(acc[nt][mt][2] + b0, acc[nt][mt][3] + b1);
            *reinterpret_cast<float2*>(&Tb[(size_t)n       * M2_ + m]) = v0;
            *reinterpret_cast<float2*>(&Tb[(size_t)(n + 8) * M2_ + m]) = v1;
        }
    }
}

// ---------------------------------------------------------------------------
// Kernel 3: gather + max + relu (bias already folded into T's center half).
// out[b][o][n] = relu( max_k( T[b][ci][o] + T[b][ni][384+o] ) )
// Block = 8 consecutive n; 384 threads = one o each. Reads coalesced over o;
// each thread buffers 8 results and writes two float4 (coalesced 32B sectors).
// ---------------------------------------------------------------------------
__global__ __launch_bounds__(384) void gather_max_kernel(
    const int* __restrict__ e,
    float* __restrict__ out,
    int estride)
{
    const int bx = blockIdx.x;              // b * 392 + group
    const int b  = bx / (NP_ / 8);
    const int n0 = (bx % (NP_ / 8)) * 8;

    __shared__ int ci[8][K_], ni[8][K_];
    const int tid = threadIdx.x;
    if (tid < 8 * K_) {
        const int j = tid / K_, k = tid % K_;
        const size_t ebase = ((size_t)(b * NP_ + n0 + j) * K_ + k) * estride;
        const size_t half  = (size_t)B_ * NP_ * K_ * estride;
        int nv = e[ebase];          // edge_index[0] = neighbor
        int cv = e[half + ebase];   // edge_index[1] = center
        ni[j][k] = min(max(nv, 0), NP_ - 1);
        ci[j][k] = min(max(cv, 0), NP_ - 1);
    }
    __syncthreads();

    const float* Tb = &g_T[(size_t)b * NP_ * M2_];
    const int o = tid;   // 0..383

    float v[8];
    #pragma unroll
    for (int j = 0; j < 8; ++j) {
        float m = -CUDART_INF_F;
        #pragma unroll
        for (int k = 0; k < K_; ++k) {
            float s = __ldg(&Tb[(size_t)ci[j][k] * M2_ + o]) +
                      __ldg(&Tb[(size_t)ni[j][k] * M2_ + COUT_ + o]);
            m = fmaxf(m, s);
        }
        v[j] = fmaxf(m, 0.f);
    }

    float* dst = &out[((size_t)b * COUT_ + o) * NP_ + n0];
    *reinterpret_cast<float4*>(dst)     = make_float4(v[0], v[1], v[2], v[3]);
    *reinterpret_cast<float4*>(dst + 4) = make_float4(v[4], v[5], v[6], v[7]);
}

// ---------------------------------------------------------------------------
extern "C" void kernel_launch(void* const* d_in, const int* in_sizes, int n_in,
                              void* d_out, int out_size) {
    const float* x    = (const float*)d_in[0];
    const int*   e    = (const int*)d_in[1];
    const float* W    = (const float*)d_in[2];
    const float* bias = (const float*)d_in[3];
    float*       out  = (float*)d_out;

    // int64 edge indices may be materialized as int32 (stride 1) or raw
    // int64 bytes viewed as int32 (stride 2, little-endian low word first).
    const int n_edge_logical = 2 * B_ * NP_ * K_;
    const int estride = (in_sizes[1] >= 2 * n_edge_logical) ? 2 : 1;

    prep_w_kernel<<<(C_ * M2_ + 255) / 256, 256>>>(W);

    dim3 gemm_grid(M2_ / 128, NP_ / 64, B_);   // (6, 49, 8)
    gemm_tf32_kernel<<<gemm_grid, 256>>>(x, bias);

    gather_max_kernel<<<B_ * (NP_ / 8), 384>>>(e, out, estride);
}

// round 14
// speedup vs baseline: 2.6750x; 1.0086x over previous
#include <cuda_runtime.h>
#include <cuda_bf16.h>
#include <math_constants.h>

// Problem constants
#define B_    8
#define C_    192
#define NP_   3136
#define K_    9
#define COUT_ 384
#define M2_   768   // 2*COUT rows in fused weight

// Scratch (device globals)
__device__ float g_Wt[C_ * M2_];                     // fused weight, [k][m], tf32-rounded
__device__ float g_T[(size_t)B_ * NP_ * M2_];        // table [B][N][768] ~77MB

__device__ __forceinline__ unsigned f2tf32(float f) {
    unsigned r;
    asm("cvt.rna.tf32.f32 %0, %1;" : "=r"(r) : "f"(f));
    return r;
}

// ---------------------------------------------------------------------------
// Kernel 1: build fused, transposed, tf32-rounded weight g_Wt[k][m]:
//   m <  384: Wc[m][k] = W[m][k] - W[m][C+k]   (center)
//   m >= 384: Wn[m'][k] = W[m'][C+k]           (neighbor), m' = m-384
// W layout: [COUT][2C] row-major.
// ---------------------------------------------------------------------------
__global__ void prep_w_kernel(const float* __restrict__ W) {
    int i = blockIdx.x * 256 + threadIdx.x;
    if (i >= C_ * M2_) return;
    int k = i / M2_;
    int m = i % M2_;
    float v;
    if (m < COUT_) {
        v = W[m * (2 * C_) + k] - W[m * (2 * C_) + C_ + k];
    } else {
        v = W[(m - COUT_) * (2 * C_) + C_ + k];
    }
    unsigned t = f2tf32(v);
    g_Wt[i] = __uint_as_float(t);
}

// ---------------------------------------------------------------------------
// Kernel 2: tf32 tensor-core GEMM
//   T[b][n][m] = sum_k x[b][k][n] * Wt[k][m]   (+ bias[m] for m<384)
// mma.m16n8k8: mma-M = n (16), mma-N = m (8), mma-K = k (8).
// Block tile: 64n x 128m, 256 threads = 8 warps (2 n-warps x 4 m-warps),
// warp tile 32n x 32m. K chunked by 16, double-buffered smem.
// ---------------------------------------------------------------------------
#define KC 16
#define XPAD 68    // 64 + 4 (68*4=272 bytes, 16B aligned rows, 2-way LDS conflicts max)
#define WPAD 132   // 128 + 4 (528 bytes, 16B aligned rows)

__global__ __launch_bounds__(256) void gemm_tf32_kernel(
    const float* __restrict__ x, const float* __restrict__ bias)
{
    __shared__ float Xs[2][KC][XPAD];   // [stage][k][n]
    __shared__ float Ws[2][KC][WPAD];   // [stage][k][m]

    const int b  = blockIdx.z;
    const int m0 = blockIdx.x * 128;    // 0..5 * 128
    const int n0 = blockIdx.y * 64;     // 0..48 * 64

    const float* xb = x + (size_t)b * C_ * NP_;

    const int tid  = threadIdx.x;
    const int warp = tid >> 5;
    const int lane = tid & 31;
    const int g    = lane >> 2;         // groupID 0..7
    const int tig  = lane & 3;          // thread-in-group 0..3
    const int wn   = warp & 1;          // n-warp: offset 32*wn
    const int wm   = warp >> 1;         // m-warp: offset 32*wm
    const int nW   = wn * 32;
    const int mW   = wm * 32;

    float acc[2][4][4];
    #pragma unroll
    for (int nt = 0; nt < 2; ++nt)
        #pragma unroll
        for (int mt = 0; mt < 4; ++mt)
            #pragma unroll
            for (int r = 0; r < 4; ++r) acc[nt][mt][r] = 0.f;

    // ---- tile loader: chunk c (k0 = c*KC) into stage s ----
    auto load_stage = [&](int s, int c) {
        const int k0 = c * KC;
        // X: 16k x 64n = 256 float4, one per thread
        {
            int kk = tid >> 4;          // 0..15
            int nq = tid & 15;          // 0..15
            const float4 v = *reinterpret_cast<const float4*>(
                &xb[(size_t)(k0 + kk) * NP_ + n0 + nq * 4]);
            float4 t;
            t.x = __uint_as_float(f2tf32(v.x));
            t.y = __uint_as_float(f2tf32(v.y));
            t.z = __uint_as_float(f2tf32(v.z));
            t.w = __uint_as_float(f2tf32(v.w));
            *reinterpret_cast<float4*>(&Xs[s][kk][nq * 4]) = t;
        }
        // W: 16k x 128m = 512 float4, two per thread (already tf32-rounded)
        #pragma unroll
        for (int r = 0; r < 2; ++r) {
            int i  = tid + r * 256;
            int kk = i >> 5;            // 0..15
            int mq = i & 31;            // 0..31
            const float4 v = *reinterpret_cast<const float4*>(
                &g_Wt[(size_t)(k0 + kk) * M2_ + m0 + mq * 4]);
            *reinterpret_cast<float4*>(&Ws[s][kk][mq * 4]) = v;
        }
    };

    load_stage(0, 0);
    __syncthreads();

    const int NCHUNK = C_ / KC;   // 12
    for (int c = 0; c < NCHUNK; ++c) {
        const int s = c & 1;
        if (c + 1 < NCHUNK) load_stage(s ^ 1, c + 1);

        #pragma unroll
        for (int ks = 0; ks < 2; ++ks) {
            const int kb = ks * 8;
            unsigned a[2][4], bf[4][2];
            // A fragments (rows = n, cols = k):
            // a0:(n+g, k+tig) a1:(n+g+8, k+tig) a2:(n+g, k+tig+4) a3:(n+g+8, k+tig+4)
            #pragma unroll
            for (int nt = 0; nt < 2; ++nt) {
                const int nb = nW + nt * 16;
                a[nt][0] = __float_as_uint(Xs[s][kb + tig    ][nb + g    ]);
                a[nt][1] = __float_as_uint(Xs[s][kb + tig    ][nb + g + 8]);
                a[nt][2] = __float_as_uint(Xs[s][kb + tig + 4][nb + g    ]);
                a[nt][3] = __float_as_uint(Xs[s][kb + tig + 4][nb + g + 8]);
            }
            // B fragments (rows = k, cols = m): b0:(k+tig, m+g) b1:(k+tig+4, m+g)
            #pragma unroll
            for (int mt = 0; mt < 4; ++mt) {
                const int mb = mW + mt * 8;
                bf[mt][0] = __float_as_uint(Ws[s][kb + tig    ][mb + g]);
                bf[mt][1] = __float_as_uint(Ws[s][kb + tig + 4][mb + g]);
            }
            #pragma unroll
            for (int nt = 0; nt < 2; ++nt)
                #pragma unroll
                for (int mt = 0; mt < 4; ++mt) {
                    asm volatile(
                        "mma.sync.aligned.m16n8k8.row.col.f32.tf32.tf32.f32 "
                        "{%0,%1,%2,%3}, {%4,%5,%6,%7}, {%8,%9}, {%0,%1,%2,%3};"
                        : "+f"(acc[nt][mt][0]), "+f"(acc[nt][mt][1]),
                          "+f"(acc[nt][mt][2]), "+f"(acc[nt][mt][3])
                        : "r"(a[nt][0]), "r"(a[nt][1]), "r"(a[nt][2]), "r"(a[nt][3]),
                          "r"(bf[mt][0]), "r"(bf[mt][1]));
                }
        }
        __syncthreads();
    }

    // ---- epilogue: + bias (center half only), write T[b][n][m] ----
    // D layout: c0:(row g, col tig*2) c1:(g, tig*2+1) c2:(g+8, tig*2) c3:(g+8, tig*2+1)
    const bool addb = (m0 < COUT_);   // 384 boundary is 128-aligned -> uniform per block
    float* Tb = &g_T[(size_t)b * NP_ * M2_];
    #pragma unroll
    for (int nt = 0; nt < 2; ++nt) {
        #pragma unroll
        for (int mt = 0; mt < 4; ++mt) {
            const int n = n0 + nW + nt * 16 + g;
            const int m = m0 + mW + mt * 8 + tig * 2;
            float b0 = 0.f, b1 = 0.f;
            if (addb) { b0 = bias[m]; b1 = bias[m + 1]; }
            float2 v0 = make_float2(acc[nt][mt][0] + b0, acc[nt][mt][1] + b1);
            float2 v1 = make_float2(acc[nt][mt][2] + b0, acc[nt][mt][3] + b1);
            *reinterpret_cast<float2*>(&Tb[(size_t)n       * M2_ + m]) = v0;
            *reinterpret_cast<float2*>(&Tb[(size_t)(n + 8) * M2_ + m]) = v1;
        }
    }
}

// ---------------------------------------------------------------------------
// Kernel 3: gather + max + relu (bias already folded into T's center half).
// out[b][o][n] = relu( max_k( T[b][ci][o] + T[b][ni][384+o] ) )
// Block = 8 consecutive n; 384 threads = one o each. Reads coalesced over o;
// each thread buffers 8 results and writes two float4 (coalesced 32B sectors).
// ---------------------------------------------------------------------------
__global__ __launch_bounds__(384) void gather_max_kernel(
    const int* __restrict__ e,
    float* __restrict__ out,
    int estride)
{
    const int bx = blockIdx.x;              // b * 392 + group
    const int b  = bx / (NP_ / 8);
    const int n0 = (bx % (NP_ / 8)) * 8;

    __shared__ int ci[8][K_], ni[8][K_];
    const int tid = threadIdx.x;
    if (tid < 8 * K_) {
        const int j = tid / K_, k = tid % K_;
        const size_t ebase = ((size_t)(b * NP_ + n0 + j) * K_ + k) * estride;
        const size_t half  = (size_t)B_ * NP_ * K_ * estride;
        int nv = e[ebase];          // edge_index[0] = neighbor
        int cv = e[half + ebase];   // edge_index[1] = center
        ni[j][k] = min(max(nv, 0), NP_ - 1);
        ci[j][k] = min(max(cv, 0), NP_ - 1);
    }
    __syncthreads();

    const float* Tb = &g_T[(size_t)b * NP_ * M2_];
    const int o = tid;   // 0..383

    float v[8];
    #pragma unroll
    for (int j = 0; j < 8; ++j) {
        float m = -CUDART_INF_F;
        #pragma unroll
        for (int k = 0; k < K_; ++k) {
            float s = __ldg(&Tb[(size_t)ci[j][k] * M2_ + o]) +
                      __ldg(&Tb[(size_t)ni[j][k] * M2_ + COUT_ + o]);
            m = fmaxf(m, s);
        }
        v[j] = fmaxf(m, 0.f);
    }

    float* dst = &out[((size_t)b * COUT_ + o) * NP_ + n0];
    *reinterpret_cast<float4*>(dst)     = make_float4(v[0], v[1], v[2], v[3]);
    *reinterpret_cast<float4*>(dst + 4) = make_float4(v[4], v[5], v[6], v[7]);
}

// ---------------------------------------------------------------------------
extern "C" void kernel_launch(void* const* d_in, const int* in_sizes, int n_in,
                              void* d_out, int out_size) {
    const float* x    = (const float*)d_in[0];
    const int*   e    = (const int*)d_in[1];
    const float* W    = (const float*)d_in[2];
    const float* bias = (const float*)d_in[3];
    float*       out  = (float*)d_out;

    // int64 edge indices may be materialized as int32 (stride 1) or raw
    // int64 bytes viewed as int32 (stride 2, little-endian low word first).
    const int n_edge_logical = 2 * B_ * NP_ * K_;
    const int estride = (in_sizes[1] >= 2 * n_edge_logical) ? 2 : 1;

    prep_w_kernel<<<(C_ * M2_ + 255) / 256, 256>>>(W);

    dim3 gemm_grid(M2_ / 128, NP_ / 64, B_);   // (6, 49, 8)
    gemm_tf32_kernel<<<gemm_grid, 256>>>(x, bias);

    gather_max_kernel<<<B_ * (NP_ / 8), 384>>>(e, out, estride);
}

// round 15
// speedup vs baseline: 2.7871x; 1.0419x over previous
#include <cuda_runtime.h>
#include <cuda_fp16.h>
#include <cuda_bf16.h>
#include <math_constants.h>

// Problem constants
#define B_    8
#define C_    192
#define NP_   3136
#define K_    9
#define COUT_ 384
#define M2_   768   // 2*COUT rows in fused weight

// Scratch (device globals)
__device__ float  g_Wt[C_ * M2_];                    // fused weight, [k][m], tf32-rounded
__device__ __half g_Th[(size_t)B_ * NP_ * M2_];      // table [B][N][768] fp16, 38.5MB

__device__ __forceinline__ unsigned f2tf32(float f) {
    unsigned r;
    asm("cvt.rna.tf32.f32 %0, %1;" : "=r"(r) : "f"(f));
    return r;
}

// ---------------------------------------------------------------------------
// Kernel 1: fused, transposed, tf32-rounded weight g_Wt[k][m]:
//   m <  384: Wc[m][k] = W[m][k] - W[m][C+k]   (center)
//   m >= 384: Wn[m'][k] = W[m'][C+k]           (neighbor), m' = m-384
// ---------------------------------------------------------------------------
__global__ void prep_w_kernel(const float* __restrict__ W) {
    int i = blockIdx.x * 256 + threadIdx.x;
    if (i >= C_ * M2_) return;
    int k = i / M2_;
    int m = i % M2_;
    float v;
    if (m < COUT_) {
        v = W[m * (2 * C_) + k] - W[m * (2 * C_) + C_ + k];
    } else {
        v = W[(m - COUT_) * (2 * C_) + C_ + k];
    }
    g_Wt[i] = __uint_as_float(f2tf32(v));
}

// ---------------------------------------------------------------------------
// Kernel 2: tf32 tensor-core GEMM
//   T[b][n][m] = sum_k x[b][k][n] * Wt[k][m]  (+ bias[m] for m<384), -> fp16
// mma.m16n8k8: mma-M = n (16), mma-N = m (8), mma-K = k (8).
// Block tile: 64n x 256m, 256 threads = 8 warps (2 n-warps x 4 m-warps),
// warp tile 32n x 64m (1.5 LDS per MMA). KC=8 per chunk, double-buffered.
// ---------------------------------------------------------------------------
#define KC 8
#define XPAD 68    // 64 + 4
#define WPAD 260   // 256 + 4

__global__ __launch_bounds__(256) void gemm_tf32_kernel(
    const float* __restrict__ x, const float* __restrict__ bias)
{
    __shared__ float Xs[2][KC][XPAD];   // [stage][k][n]   4.4 KB
    __shared__ float Ws[2][KC][WPAD];   // [stage][k][m]  16.6 KB

    const int b  = blockIdx.z;
    const int m0 = blockIdx.x * 256;    // 0..2 * 256
    const int n0 = blockIdx.y * 64;     // 0..48 * 64

    const float* xb = x + (size_t)b * C_ * NP_;

    const int tid  = threadIdx.x;
    const int warp = tid >> 5;
    const int lane = tid & 31;
    const int g    = lane >> 2;         // groupID 0..7
    const int tig  = lane & 3;          // thread-in-group 0..3
    const int nW   = (warp & 1) * 32;   // n-warp offset
    const int mW   = (warp >> 1) * 64;  // m-warp offset

    float acc[2][8][4];
    #pragma unroll
    for (int nt = 0; nt < 2; ++nt)
        #pragma unroll
        for (int mt = 0; mt < 8; ++mt)
            #pragma unroll
            for (int r = 0; r < 4; ++r) acc[nt][mt][r] = 0.f;

    // ---- tile loader: chunk c (k0 = c*KC) into stage s ----
    auto load_stage = [&](int s, int c) {
        const int k0 = c * KC;
        // X: 8k x 64n = 128 float4 (threads 0..127)
        if (tid < 128) {
            int kk = tid >> 4;          // 0..7
            int nq = tid & 15;          // 0..15
            const float4 v = *reinterpret_cast<const float4*>(
                &xb[(size_t)(k0 + kk) * NP_ + n0 + nq * 4]);
            float4 t;
            t.x = __uint_as_float(f2tf32(v.x));
            t.y = __uint_as_float(f2tf32(v.y));
            t.z = __uint_as_float(f2tf32(v.z));
            t.w = __uint_as_float(f2tf32(v.w));
            *reinterpret_cast<float4*>(&Xs[s][kk][nq * 4]) = t;
        }
        // W: 8k x 256m = 512 float4, two per thread (already tf32-rounded)
        #pragma unroll
        for (int r = 0; r < 2; ++r) {
            int i  = tid + r * 256;
            int kk = i >> 6;            // 0..7
            int mq = i & 63;            // 0..63
            const float4 v = *reinterpret_cast<const float4*>(
                &g_Wt[(size_t)(k0 + kk) * M2_ + m0 + mq * 4]);
            *reinterpret_cast<float4*>(&Ws[s][kk][mq * 4]) = v;
        }
    };

    load_stage(0, 0);
    __syncthreads();

    const int NCHUNK = C_ / KC;   // 24
    for (int c = 0; c < NCHUNK; ++c) {
        const int s = c & 1;
        if (c + 1 < NCHUNK) load_stage(s ^ 1, c + 1);

        unsigned a[2][4], bf[8][2];
        // A fragments (rows = n, cols = k)
        #pragma unroll
        for (int nt = 0; nt < 2; ++nt) {
            const int nb = nW + nt * 16;
            a[nt][0] = __float_as_uint(Xs[s][tig    ][nb + g    ]);
            a[nt][1] = __float_as_uint(Xs[s][tig    ][nb + g + 8]);
            a[nt][2] = __float_as_uint(Xs[s][tig + 4][nb + g    ]);
            a[nt][3] = __float_as_uint(Xs[s][tig + 4][nb + g + 8]);
        }
        // B fragments (rows = k, cols = m)
        #pragma unroll
        for (int mt = 0; mt < 8; ++mt) {
            const int mb = mW + mt * 8;
            bf[mt][0] = __float_as_uint(Ws[s][tig    ][mb + g]);
            bf[mt][1] = __float_as_uint(Ws[s][tig + 4][mb + g]);
        }
        #pragma unroll
        for (int nt = 0; nt < 2; ++nt)
            #pragma unroll
            for (int mt = 0; mt < 8; ++mt) {
                asm volatile(
                    "mma.sync.aligned.m16n8k8.row.col.f32.tf32.tf32.f32 "
                    "{%0,%1,%2,%3}, {%4,%5,%6,%7}, {%8,%9}, {%0,%1,%2,%3};"
                    : "+f"(acc[nt][mt][0]), "+f"(acc[nt][mt][1]),
                      "+f"(acc[nt][mt][2]), "+f"(acc[nt][mt][3])
                    : "r"(a[nt][0]), "r"(a[nt][1]), "r"(a[nt][2]), "r"(a[nt][3]),
                      "r"(bf[mt][0]), "r"(bf[mt][1]));
            }
        __syncthreads();
    }

    // ---- epilogue: + bias (center half), convert to fp16, write T ----
    // D layout: c0:(row g, col tig*2) c1:(g, tig*2+1) c2:(g+8, tig*2) c3:(g+8, tig*2+1)
    __half* Tb = &g_Th[(size_t)b * NP_ * M2_];
    #pragma unroll
    for (int nt = 0; nt < 2; ++nt) {
        #pragma unroll
        for (int mt = 0; mt < 8; ++mt) {
            const int n = n0 + nW + nt * 16 + g;
            const int m = m0 + mW + mt * 8 + tig * 2;   // even; m,m+1 same side of 384
            float b0 = 0.f, b1 = 0.f;
            if (m < COUT_) { b0 = bias[m]; b1 = bias[m + 1]; }
            __half2 h0 = __floats2half2_rn(acc[nt][mt][0] + b0, acc[nt][mt][1] + b1);
            __half2 h1 = __floats2half2_rn(acc[nt][mt][2] + b0, acc[nt][mt][3] + b1);
            *reinterpret_cast<__half2*>(&Tb[(size_t)n       * M2_ + m]) = h0;
            *reinterpret_cast<__half2*>(&Tb[(size_t)(n + 8) * M2_ + m]) = h1;
        }
    }
}

// ---------------------------------------------------------------------------
// Kernel 3: gather + max + relu (bias already folded into T's center half).
// out[b][o][n] = relu( max_k( T[b][ci][o] + T[b][ni][384+o] ) )
// Block = 8 consecutive n; 192 threads, each owns an o-pair (half2 loads,
// fp32 add/max). Reads coalesced over o (128B/warp); each thread buffers
// 2 rows x 8 n and writes four float4.
// ---------------------------------------------------------------------------
__global__ __launch_bounds__(192) void gather_max_kernel(
    const int* __restrict__ e,
    float* __restrict__ out,
    int estride)
{
    const int bx = blockIdx.x;              // b * 392 + group
    const int b  = bx / (NP_ / 8);
    const int n0 = (bx % (NP_ / 8)) * 8;

    __shared__ int ci[8][K_], ni[8][K_];
    const int tid = threadIdx.x;
    if (tid < 8 * K_) {
        const int j = tid / K_, k = tid % K_;
        const size_t ebase = ((size_t)(b * NP_ + n0 + j) * K_ + k) * estride;
        const size_t half  = (size_t)B_ * NP_ * K_ * estride;
        int nv = e[ebase];          // edge_index[0] = neighbor
        int cv = e[half + ebase];   // edge_index[1] = center
        ni[j][k] = min(max(nv, 0), NP_ - 1);
        ci[j][k] = min(max(cv, 0), NP_ - 1);
    }
    __syncthreads();

    const __half* Tb = &g_Th[(size_t)b * NP_ * M2_];
    const int o0 = tid * 2;   // 0..382, even

    float v0[8], v1[8];
    #pragma unroll
    for (int j = 0; j < 8; ++j) {
        float m0f = -CUDART_INF_F, m1f = -CUDART_INF_F;
        #pragma unroll
        for (int k = 0; k < K_; ++k) {
            __half2 hc = *reinterpret_cast<const __half2*>(
                &Tb[(size_t)ci[j][k] * M2_ + o0]);
            __half2 hn = *reinterpret_cast<const __half2*>(
                &Tb[(size_t)ni[j][k] * M2_ + COUT_ + o0]);
            float2 cf = __half22float2(hc);
            float2 nf = __half22float2(hn);
            m0f = fmaxf(m0f, cf.x + nf.x);
            m1f = fmaxf(m1f, cf.y + nf.y);
        }
        v0[j] = fmaxf(m0f, 0.f);
        v1[j] = fmaxf(m1f, 0.f);
    }

    float* d0 = &out[((size_t)b * COUT_ + o0) * NP_ + n0];
    float* d1 = d0 + NP_;   // row o0+1
    *reinterpret_cast<float4*>(d0)     = make_float4(v0[0], v0[1], v0[2], v0[3]);
    *reinterpret_cast<float4*>(d0 + 4) = make_float4(v0[4], v0[5], v0[6], v0[7]);
    *reinterpret_cast<float4*>(d1)     = make_float4(v1[0], v1[1], v1[2], v1[3]);
    *reinterpret_cast<float4*>(d1 + 4) = make_float4(v1[4], v1[5], v1[6], v1[7]);
}

// ---------------------------------------------------------------------------
extern "C" void kernel_launch(void* const* d_in, const int* in_sizes, int n_in,
                              void* d_out, int out_size) {
    const float* x    = (const float*)d_in[0];
    const int*   e    = (const int*)d_in[1];
    const float* W    = (const float*)d_in[2];
    const float* bias = (const float*)d_in[3];
    float*       out  = (float*)d_out;

    // int64 edge indices may be materialized as int32 (stride 1) or raw
    // int64 bytes viewed as int32 (stride 2, little-endian low word first).
    const int n_edge_logical = 2 * B_ * NP_ * K_;
    const int estride = (in_sizes[1] >= 2 * n_edge_logical) ? 2 : 1;

    prep_w_kernel<<<(C_ * M2_ + 255) / 256, 256>>>(W);

    dim3 gemm_grid(M2_ / 256, NP_ / 64, B_);   // (3, 49, 8)
    gemm_tf32_kernel<<<gemm_grid, 256>>>(x, bias);

    gather_max_kernel<<<B_ * (NP_ / 8), 192>>>(e, out, estride);
}